// round 17
// baseline (speedup 1.0000x reference)
#include <cuda_runtime.h>
#include <cstdint>

// ExpandHarmonics: N=2e6 rows, MAX_MULT=5 harmonics per row.
// Output layout (concatenated flattened tuple, float32):
//   [0,15N) hkl_all | [15N,20N) wavelength_all | [20N,25N) d_all | [25N,30N) refl_id

#define HMAX_C 60
#define G_C    121
#define MAX_MULT_C 5
#define BLOCK 128
#define RPT   2                      // rows per thread
#define TILE  (BLOCK * RPT)          // 256 rows per CTA

#define INV_WMIN (1.0f / 0.95f)
#define INV_WMAX 0.8f                // 1/1.25

// gcd table for a,b in [0,12]
__device__ const unsigned char GTAB[169] = {
    0,1,2,3,4,5,6,7,8,9,10,11,12,
    1,1,1,1,1,1,1,1,1,1,1,1,1,
    2,1,2,1,2,1,2,1,2,1,2,1,2,
    3,1,1,3,1,1,3,1,1,3,1,1,3,
    4,1,2,1,4,1,2,1,4,1,2,1,4,
    5,1,1,1,1,5,1,1,1,1,5,1,1,
    6,1,2,3,2,1,6,1,2,3,2,1,6,
    7,1,1,1,1,1,1,7,1,1,1,1,1,
    8,1,2,1,4,1,2,1,8,1,2,1,4,
    9,1,1,3,1,1,3,1,1,9,1,1,3,
    10,1,2,1,2,5,2,1,2,1,10,1,2,
    11,1,1,1,1,1,1,1,1,1,1,11,1,
    12,1,2,3,4,1,6,1,4,3,2,1,12
};

__device__ __forceinline__ int ldg_policy(const int* p, uint64_t policy) {
    int v;
    asm volatile("ld.global.nc.L2::cache_hint.b32 %0, [%1], %2;"
                 : "=r"(v) : "l"(p), "l"(policy));
    return v;
}

__device__ __forceinline__ void bulk_store_s2g_ef(void* gdst, const void* ssrc, int bytes,
                                                  uint64_t policy) {
    uint32_t s = (uint32_t)__cvta_generic_to_shared(ssrc);
    asm volatile("cp.async.bulk.global.shared::cta.bulk_group.L2::cache_hint"
                 " [%0], [%1], %2, %3;"
                 :: "l"(gdst), "r"(s), "r"(bytes), "l"(policy) : "memory");
}

__global__ __launch_bounds__(BLOCK, 7)
void expand_harmonics_kernel(const int*   __restrict__ asu_id,
                             const int*   __restrict__ hkl,
                             const float* __restrict__ wl,
                             const float* __restrict__ dmin,
                             const float* __restrict__ Bmat,
                             const int*   __restrict__ refl,
                             float*       __restrict__ out,
                             int N)
{
    __shared__ float sB[36];
    __shared__ float srdmin[4];
    __shared__ float srcp[32];
    __shared__ unsigned char sg[169];
    __shared__ __align__(16) float s_hkl[TILE * 15];
    __shared__ __align__(16) float s_wl [TILE * 5];
    __shared__ __align__(16) float s_d  [TILE * 5];
    __shared__ __align__(16) float s_id [TILE * 5];

    const int t = threadIdx.x;
    if (t < 36)  sB[t] = Bmat[t];
    if (t < 4)   srdmin[t] = 1.0f / dmin[t];
    if (t < 32)  srcp[t] = 1.0f / (float)max(t, 1);
    {
        if (t < 128)       sg[t]       = GTAB[t];
        if (t < 169 - 128) sg[t + 128] = GTAB[t + 128];
    }
    __syncthreads();

    uint64_t pol_keep;
    asm volatile("createpolicy.fractional.L2::evict_last.b64 %0, 1.0;" : "=l"(pol_keep));

    const int r0 = blockIdx.x * TILE;
    const int nv = min(TILE, N - r0);

    // Per-row state, 2 rows per thread
    int   h0[RPT], k0[RPT], l0[RPT];
    float d0[RPT], wl0[RPT];
    bool  mask_[RPT], act[RPT];
    int   ni_a[RPT][MAX_MULT_C];
    int   rid [RPT][MAX_MULT_C];

    // ---- Phase A (both rows): loads + row math + issue ALL gathers (MLP=10) ----
    #pragma unroll
    for (int rr = 0; rr < RPT; rr++) {
        const int row = t + rr * BLOCK;       // row within tile
        const int i   = r0 + row;
        act[rr] = (row < nv);
        #pragma unroll
        for (int j = 0; j < MAX_MULT_C; j++) { rid[rr][j] = -1; ni_a[rr][j] = 0; }
        h0[rr] = k0[rr] = l0[rr] = 0; d0[rr] = wl0[rr] = 0.f; mask_[rr] = false;

        if (act[rr]) {
            const int a = asu_id[i];
            const int h = hkl[3 * i + 0];
            const int k = hkl[3 * i + 1];
            const int l = hkl[3 * i + 2];
            const float w = wl[i];

            const int ah = abs(h), ak = abs(k), al = abs(l);
            mask_[rr] = ((ah | ak | al) != 0);

            const int g1 = sg[ah * 13 + ak];
            const int n  = sg[g1 * 13 + al];
            const int ns = max(n, 1);

            const float rcp = srcp[ns];
            h0[rr] = __float2int_rn((float)h * rcp);
            k0[rr] = __float2int_rn((float)k * rcp);
            l0[rr] = __float2int_rn((float)l * rcp);

            wl0[rr] = w * (float)ns;

            const float* Bm = sB + a * 9;
            const float fh = (float)h0[rr], fk = (float)k0[rr], fl = (float)l0[rr];
            const float s0 = Bm[0] * fh + Bm[1] * fk + Bm[2] * fl;
            const float s1 = Bm[3] * fh + Bm[4] * fk + Bm[5] * fl;
            const float s2 = Bm[6] * fh + Bm[7] * fk + Bm[8] * fl;
            const float nrm2 = s0 * s0 + s1 * s1 + s2 * s2;
            d0[rr] = rsqrtf(fmaxf(nrm2, 1e-12f));

            const float nmax = fminf(floorf(d0[rr] * srdmin[a]), floorf(wl0[rr] * INV_WMIN));
            const float nmin = floorf(wl0[rr] * INV_WMAX) + 1.0f;

            const int step  = (h0[rr] * G_C + k0[rr]) * G_C + l0[rr];
            const int base0 = a * (G_C * G_C * G_C) + HMAX_C * (G_C * G_C + G_C + 1);
            const int m = max(max(abs(h0[rr]), abs(k0[rr])), abs(l0[rr]));

            #pragma unroll
            for (int j = 0; j < MAX_MULT_C; j++) {
                float na = nmin + (float)j;
                if (na > nmax) na = 0.0f;
                const int ni = (int)na;     // 0..17
                ni_a[rr][j] = ni;
                // ni==0 hits the table center which is always -1 -> skip load
                if (ni > 0 && ni * m <= HMAX_C)
                    rid[rr][j] = ldg_policy(&refl[base0 + ni * step], pol_keep);
            }
        }
    }

    // ---- Phase B (both rows): consume gathers, stage outputs ----
    #pragma unroll
    for (int rr = 0; rr < RPT; rr++) {
        if (act[rr]) {
            const int row = t + rr * BLOCK;
            #pragma unroll
            for (int j = 0; j < MAX_MULT_C; j++) {
                const int ni = ni_a[rr][j];
                const bool absent = (rid[rr][j] < 0);
                const int   ne   = absent ? 0 : ni;
                const float ninv = absent ? 0.0f : srcp[ni];   // == 1.0f/na exactly

                s_hkl[row * 15 + 3 * j + 0] = (float)(h0[rr] * ne);
                s_hkl[row * 15 + 3 * j + 1] = (float)(k0[rr] * ne);
                s_hkl[row * 15 + 3 * j + 2] = (float)(l0[rr] * ne);
                s_wl [row * 5 + j] = wl0[rr] * ninv;
                s_d  [row * 5 + j] = d0[rr]  * ninv;
                s_id [row * 5 + j] = (float)(mask_[rr] ? rid[rr][j] : 0);
            }
        }
    }
    __syncthreads();

    // ---- Copy-out: 4 bulk stores distributed over 4 warps ----
    const long b15 = (long)nv * 15 * 4;
    const long b5  = (long)nv * 5 * 4;

    const bool tma_ok = ((b15 & 15) == 0) && ((b5 & 15) == 0) &&
                        ((((long)N * 60) & 15) == 0) && ((((long)r0 * 20) & 15) == 0);

    if (tma_ok) {
        if ((t & 31) == 0) {
            const int wg = t >> 5;            // 0..3
            uint64_t pol_stream;
            asm volatile("createpolicy.fractional.L2::evict_first.b64 %0, 1.0;"
                         : "=l"(pol_stream));
            asm volatile("fence.proxy.async.shared::cta;" ::: "memory");
            if      (wg == 0) bulk_store_s2g_ef(out + (size_t)r0 * 15,                 s_hkl, (int)b15, pol_stream);
            else if (wg == 1) bulk_store_s2g_ef(out + (size_t)N * 15 + (size_t)r0 * 5, s_wl,  (int)b5,  pol_stream);
            else if (wg == 2) bulk_store_s2g_ef(out + (size_t)N * 20 + (size_t)r0 * 5, s_d,   (int)b5,  pol_stream);
            else              bulk_store_s2g_ef(out + (size_t)N * 25 + (size_t)r0 * 5, s_id,  (int)b5,  pol_stream);
            asm volatile("cp.async.bulk.commit_group;" ::: "memory");
            asm volatile("cp.async.bulk.wait_group.read 0;" ::: "memory");
        }
    } else {
        float* o0 = out + (size_t)r0 * 15;
        float* o1 = out + (size_t)N * 15 + (size_t)r0 * 5;
        float* o2 = out + (size_t)N * 20 + (size_t)r0 * 5;
        float* o3 = out + (size_t)N * 25 + (size_t)r0 * 5;
        for (int idx = t; idx < nv * 15; idx += BLOCK) o0[idx] = s_hkl[idx];
        for (int idx = t; idx < nv * 5;  idx += BLOCK) o1[idx] = s_wl[idx];
        for (int idx = t; idx < nv * 5;  idx += BLOCK) o2[idx] = s_d[idx];
        for (int idx = t; idx < nv * 5;  idx += BLOCK) o3[idx] = s_id[idx];
    }
}

extern "C" void kernel_launch(void* const* d_in, const int* in_sizes, int n_in,
                              void* d_out, int out_size)
{
    const int*   asu_id = (const int*)  d_in[0];
    const int*   hkl    = (const int*)  d_in[1];
    const float* wl     = (const float*)d_in[2];
    const float* dmin   = (const float*)d_in[3];
    const float* Bmat   = (const float*)d_in[4];
    const int*   refl   = (const int*)  d_in[5];

    const int N = in_sizes[0];
    float* out = (float*)d_out;

    const int grid = (N + TILE - 1) / TILE;
    expand_harmonics_kernel<<<grid, BLOCK>>>(asu_id, hkl, wl, dmin, Bmat, refl, out, N);
}